// round 14
// baseline (speedup 1.0000x reference)
#include <cuda_runtime.h>

#define FULLM 0xffffffffu
#define MAXN 200000
#define KSLOT 4

__device__ int g_starts[MAXN + 1];

struct KParams {
  const float2* loc;
  const float*  ts;
  const int*    cat;
  const float*  sw[16];
  const float*  wc1; const float* bc1;
  const float*  wc2; const float* bc2;
  float* out;
  int N;
};

__device__ __forceinline__ float wsum(float v){
#pragma unroll
  for (int o=16;o;o>>=1) v += __shfl_xor_sync(FULLM, v, o);
  return v;
}

// fast positive fmod: trunc-quotient + exact fma + range fixup.
__device__ __forceinline__ float fast_mod(float x, float y, float inv){
  float q = truncf(x * inv);
  float r = __fmaf_rn(-q, y, x);
  r = (r < 0.f)  ? (r + y) : r;
  r = (r >= y)   ? (r - y) : r;
  return r;
}

__global__ void starts_kernel(const int4* __restrict__ seg4,
                              const int*  __restrict__ seg, int T, int N){
  int g = blockIdx.x*blockDim.x + threadIdx.x;
  int base = g * 4;
  if (base >= T) return;
  int4 v = seg4[g];
  if (base == 0){
    g_starts[v.x] = 0;
    g_starts[N] = T;
  } else {
    int prev = seg[base-1];
    if (v.x != prev) g_starts[v.x] = base;
  }
  if (base+1 < T && v.y != v.x) g_starts[v.y] = base+1;
  if (base+2 < T && v.z != v.y) g_starts[v.z] = base+2;
  if (base+3 < T && v.w != v.z) g_starts[v.w] = base+3;
}

__global__ void __launch_bounds__(256,2) mobility_kernel(KParams p){
  __shared__ float s_w1[4096];   // interleaved: [i*64+m*2+{0,1}] = wc1[i*64+m], wc1[i*64+m+32]
  __shared__ float s_w2[4096];
  __shared__ float s_b1[64];
  __shared__ float s_b2[64];
  __shared__ float s_small[1456];
  __shared__ float4 s_stage[8*64];   // per-warp 64-row feat/hidden staging

  for (int t = threadIdx.x; t < 2048; t += blockDim.x){
    int i = t >> 5, m = t & 31;
    s_w1[2*t]   = p.wc1[i*64 + m];
    s_w1[2*t+1] = p.wc1[i*64 + m + 32];
    s_w2[2*t]   = p.wc2[i*64 + m];
    s_w2[2*t+1] = p.wc2[i*64 + m + 32];
  }
  if (threadIdx.x < 64){
    s_b1[threadIdx.x] = p.bc1[threadIdx.x];
    s_b2[threadIdx.x] = p.bc2[threadIdx.x];
  }
  {
    const int SOFF[17] = {0,32,48,304,320,368,384,640,656,816,832,1088,1104,1168,1184,1440,1456};
#pragma unroll
    for (int sg = 0; sg < 16; sg++){
      int o = SOFF[sg], n = SOFF[sg+1]-o;
      for (int t = threadIdx.x; t < n; t += blockDim.x) s_small[o+t] = p.sw[sg][t];
    }
  }
  __syncthreads();

  const int lane = threadIdx.x & 31;
  const int wid  = threadIdx.x >> 5;
  float4* stg  = &s_stage[wid * 64];
  float*  stgF = (float*)stg;
  const int gw  = (blockIdx.x*blockDim.x + threadIdx.x) >> 5;
  const int nwp = (gridDim.x*blockDim.x) >> 5;
  const float2* w1p = (const float2*)s_w1;
  const float2* w2p = (const float2*)s_w2;

  // ---- hoist small-MLP weights into registers (constant per lane) ----
  const int j    = lane & 15;
  const int half = lane >> 4;
  float rw0[3], rb0;
  {
    int w1o = half ? 320 : 0;
    int b1o = half ? 368 : 32;
    rb0 = s_small[b1o + j];
    rw0[0] = s_small[w1o +  0 + j];
    rw0[1] = s_small[w1o + 16 + j];
    rw0[2] = s_small[w1o + 32 + j];
  }
  float rw1[10], rb1;
  {
    int w1o = half ? 1104 : 656;
    int b1o = half ? 1168 : 816;
    rb1 = s_small[b1o + j];
#pragma unroll
    for (int i = 0; i < 10; i++) rw1[i] = s_small[w1o + i*16 + j];
  }
  float rf0[16], rc0;
  {
    int w2o = half ? 384 : 48;
    int b2o = half ? 640 : 304;
    rc0 = s_small[b2o + j];
#pragma unroll
    for (int i = 0; i < 16; i++) rf0[i] = s_small[w2o + i*16 + j];
  }
  float rf1[16], rc1;
  {
    int w2o = half ? 1184 : 832;
    int b2o = half ? 1440 : 1088;
    rc1 = s_small[b2o + j];
#pragma unroll
    for (int i = 0; i < 16; i++) rf1[i] = s_small[w2o + i*16 + j];
  }
  const int sb = half << 4;

  for (int base = gw*4; base < p.N; base += nwp*4){

    // =================== feature + small-MLP phase (per user) ===================
    for (int q = 0; q < 4; q++){
      int u = base + q;
      if (u >= p.N) break;                       // warp-uniform

      const int s = g_starts[u], e = g_starts[u+1];
      const int L = e - s;
      const float fL = (float)L;

      float hx, hy, t0, t1, t2, radius, diversity, freq, regl;
      unsigned hw0 = 0u, hw1 = 0u, hw2 = 0u;

      if (L <= 32*KSLOT) {
        // ---------- fast path: segment cached in registers ----------
        const int K = (L + 31) >> 5;
        float lx[KSLOT], ly[KSLOT], lt[KSLOT];
        int   lk[KSLOT];

        float sx=0.f, sy=0.f, sh=0.f, sdy=0.f, smo=0.f, sdiff=0.f;
        float tmn = 3.0e38f, tmx = 0.0f;         // ts >= 0; max init 0 is safe

#pragma unroll
        for (int a = 0; a < KSLOT; a++){
          int i = s + a*32 + lane;
          bool v = (a < K) && (i < e);
          float2 pt = make_float2(0.f, 0.f);
          float t = 0.f; int c = 12;
          if (v){ pt = p.loc[i]; t = p.ts[i]; c = p.cat[i]; }
          lx[a] = pt.x; ly[a] = pt.y; lt[a] = t;
          int kx = __float2int_rn(pt.x * 50.0f);
          int ky = __float2int_rn(pt.y * 50.0f);
          lk[a] = v ? (int)(((unsigned)(kx & 0xffff) << 16) | (unsigned)(ky & 0xffff))
                    : 0x7f000000;
          if (v){
            sx += pt.x; sy += pt.y;
            sh  += fast_mod(t, 86400.0f, 1.0f/86400.0f) * (1.0f/3600.0f);
            sdy += fast_mod(__fdiv_rn(t, 86400.0f),   7.0f, 1.0f/7.0f);
            smo += fast_mod(__fdiv_rn(t, 2592000.0f), 12.0f, 1.0f/12.0f);
            unsigned inc = 1u << ((c & 3) * 8);
            int wq = c >> 2;
            hw0 += (wq==0) ? inc : 0u;
            hw1 += (wq==1) ? inc : 0u;
            hw2 += (wq==2) ? inc : 0u;
            tmn = fminf(tmn, t); tmx = fmaxf(tmx, t);
          }
        }

        // diffs via shfl of cached timestamps
        float ld[KSLOT];
#pragma unroll
        for (int a = 0; a < KSLOT; a++){
          float up = (a+1 < KSLOT) ? __shfl_sync(FULLM, lt[a+1], 0) : 0.f;
          float nt = __shfl_down_sync(FULLM, lt[a], 1);
          if (lane == 31) nt = up;
          int i = s + a*32 + lane;
          bool hd = (a < K) && (i < e - 1);
          float d = nt - lt[a];
          ld[a] = hd ? d : 0.f;
          sdiff += hd ? d : 0.f;
        }

        sx = wsum(sx); sy = wsum(sy);
        sh = wsum(sh); sdy = wsum(sdy); smo = wsum(smo);
        sdiff = wsum(sdiff);
        hw0 = __reduce_add_sync(FULLM, hw0);
        hw1 = __reduce_add_sync(FULLM, hw1);
        hw2 = __reduce_add_sync(FULLM, hw2);
        tmn = __uint_as_float(__reduce_min_sync(FULLM, __float_as_uint(tmn)));
        tmx = __uint_as_float(__reduce_max_sync(FULLM, __float_as_uint(tmx)));

        hx = sx / fL; hy = sy / fL;
        t0 = sh / fL; t1 = sdy / fL; t2 = smo / fL;
        const float dmu  = sdiff / (fL - 1.0f);
        const float span = (tmx - tmn) / 86400.0f;
        freq = fL / fmaxf(span, 1.0f);

        float dist[KSLOT];
        float sdl = 0.f, sdv = 0.f;
#pragma unroll
        for (int a = 0; a < KSLOT; a++){
          int i = s + a*32 + lane;
          bool v = (a < K) && (i < e);
          float dx = lx[a] - hx, dy = ly[a] - hy;
          float dd = sqrtf(dx*dx + dy*dy);
          dist[a] = dd;
          sdl += v ? dd : 0.f;
          bool hd = (a < K) && (i < e - 1);
          float cdt = ld[a] - dmu;
          sdv += hd ? cdt*cdt : 0.f;
        }
        sdl = wsum(sdl); sdv = wsum(sdv);
        const float dmean = sdl / fL;
        const float dvar  = sdv / (fL - 2.0f);
        regl = 1.0f / (sqrtf(dvar) + 1e-6f);

        float srr = 0.f;
#pragma unroll
        for (int a = 0; a < KSLOT; a++){
          int i = s + a*32 + lane;
          bool v = (a < K) && (i < e);
          float r = dist[a] - dmean;
          srr += v ? r*r : 0.f;
        }
        srr = wsum(srr);
        radius = sqrtf(srr / (fL - 1.0f));

        // diversity: MATCH.ANY within slot + broadcast compare across slots
        unsigned uniqcnt = 0u;
        const unsigned ltmask = (1u << lane) - 1u;
#pragma unroll
        for (int a = 0; a < KSLOT; a++){
          if (a >= K) break;
          int i = s + a*32 + lane;
          bool valid = (i < e);
          int ka = lk[a];
          unsigned m = __match_any_sync(FULLM, ka);
          bool dup = (m & ltmask) != 0u;
#pragma unroll
          for (int b = 0; b < KSLOT-1; b++){
            if (b >= a) break;
            int kb = lk[b];
#pragma unroll
            for (int r = 0; r < 32; r++){
              int kj = __shfl_sync(FULLM, kb, r);
              dup |= (kj == ka);
            }
          }
          uniqcnt += (valid && !dup) ? 1u : 0u;
        }
        float uniq = (float)__reduce_add_sync(FULLM, uniqcnt);
        diversity = uniq / fL;

      } else {
        // ---------- fallback path (L > 128): global-load version ----------
        float sx=0.f, sy=0.f, sh=0.f, sdy=0.f, smo=0.f, sdiff=0.f;
        float tmn = 3.0e38f, tmx = 0.0f;
        for (int i = s + lane; i < e; i += 32){
          float2 pt = p.loc[i];
          float t  = p.ts[i];
          int   c  = p.cat[i];
          sx += pt.x; sy += pt.y;
          sh  += __fdiv_rn(fmodf(t, 86400.0f), 3600.0f);
          sdy += fmodf(__fdiv_rn(t, 86400.0f), 7.0f);
          smo += fmodf(__fdiv_rn(t, 2592000.0f), 12.0f);
          unsigned inc = 1u << ((c & 3) * 8);
          int wq = c >> 2;
          hw0 += (wq==0) ? inc : 0u;
          hw1 += (wq==1) ? inc : 0u;
          hw2 += (wq==2) ? inc : 0u;
          tmn = fminf(tmn, t); tmx = fmaxf(tmx, t);
          if (i + 1 < e) sdiff += p.ts[i+1] - t;
        }
        sx = wsum(sx); sy = wsum(sy);
        sh = wsum(sh); sdy = wsum(sdy); smo = wsum(smo);
        sdiff = wsum(sdiff);
        hw0 = __reduce_add_sync(FULLM, hw0);
        hw1 = __reduce_add_sync(FULLM, hw1);
        hw2 = __reduce_add_sync(FULLM, hw2);
        tmn = __uint_as_float(__reduce_min_sync(FULLM, __float_as_uint(tmn)));
        tmx = __uint_as_float(__reduce_max_sync(FULLM, __float_as_uint(tmx)));

        hx = sx / fL; hy = sy / fL;
        t0 = sh / fL; t1 = sdy / fL; t2 = smo / fL;
        const float dmu  = sdiff / (fL - 1.0f);
        const float span = (tmx - tmn) / 86400.0f;
        freq = fL / fmaxf(span, 1.0f);

        float sdl = 0.f, sdv = 0.f;
        for (int i = s + lane; i < e; i += 32){
          float2 pt = p.loc[i];
          float dx = pt.x - hx, dy = pt.y - hy;
          sdl += sqrtf(dx*dx + dy*dy);
          if (i + 1 < e){
            float dd = p.ts[i+1] - p.ts[i] - dmu;
            sdv += dd * dd;
          }
        }
        sdl = wsum(sdl); sdv = wsum(sdv);
        const float dmean = sdl / fL;
        const float dvar  = sdv / (fL - 2.0f);
        regl = 1.0f / (sqrtf(dvar) + 1e-6f);

        float srr = 0.f;
        for (int i = s + lane; i < e; i += 32){
          float2 pt = p.loc[i];
          float dx = pt.x - hx, dy = pt.y - hy;
          float r = sqrtf(dx*dx + dy*dy) - dmean;
          srr += r * r;
        }
        srr = wsum(srr);
        radius = sqrtf(srr / (fL - 1.0f));

        float uniqp = 0.f;
        for (int bb = s; bb < e; bb += 32){
          int i = bb + lane;
          bool valid = (i < e);
          float px = 0.f, py = 0.f;
          if (valid){ float2 pt = p.loc[i]; px = pt.x; py = pt.y; }
          bool dup = false;
          int jmax = min(bb + 31, e - 1);
          for (int jg = s; jg < jmax; ++jg){
            float2 qq = p.loc[jg];
            dup |= (jg < i) & (qq.x == px) & (qq.y == py);
          }
          uniqp += (valid && !dup) ? 1.f : 0.f;
        }
        float uniq = wsum(uniqp);
        diversity = uniq / fL;
      }

      // category distribution
      float actv[10];
#pragma unroll
      for (int c = 0; c < 10; c++){
        unsigned w = (c < 4) ? hw0 : ((c < 8) ? hw1 : hw2);
        unsigned cnt = (w >> ((c & 3) * 8)) & 0xffu;
        actv[c] = (float)cnt / fL;
      }

      // ---------------- small MLPs (register weights) ----------------
      float hv0;
      {
        float x0 = half ? t0 : hx;
        float x1 = half ? t1 : hy;
        float x2 = half ? t2 : 0.f;
        float a = rb0;
        a = __fmaf_rn(x0, rw0[0], a);
        a = __fmaf_rn(x1, rw0[1], a);
        a = __fmaf_rn(x2, rw0[2], a);
        hv0 = fmaxf(a, 0.f);
      }
      float hv1;
      {
        float xv[10];
        xv[0] = half ? radius    : actv[0];
        xv[1] = half ? diversity : actv[1];
        xv[2] = half ? freq      : actv[2];
        xv[3] = half ? regl      : actv[3];
#pragma unroll
        for (int i = 4; i < 10; i++) xv[i] = half ? 0.f : actv[i];
        float a = rb1;
#pragma unroll
        for (int i = 0; i < 10; i++) a = __fmaf_rn(xv[i], rw1[i], a);
        hv1 = fmaxf(a, 0.f);
      }

      float f0 = rc0, f1 = rc1;
#pragma unroll
      for (int i = 0; i < 16; i++)
        f0 = __fmaf_rn(__shfl_sync(FULLM, hv0, sb + i), rf0[i], f0);
#pragma unroll
      for (int i = 0; i < 16; i++)
        f1 = __fmaf_rn(__shfl_sync(FULLM, hv1, sb + i), rf1[i], f1);

      // stage this user's feats (component q of the float4 rows)
      stgF[lane*4 + q]      = f0;
      stgF[(32+lane)*4 + q] = f1;
    }
    __syncwarp();

    // =================== batched cmb MLP: 4 users per pass ===================
    float bi0 = s_b1[lane], bi1 = s_b1[lane + 32];
    float a00=bi0, a01=bi0, a02=bi0, a03=bi0;
    float a10=bi1, a11=bi1, a12=bi1, a13=bi1;
#pragma unroll 16
    for (int i = 0; i < 64; i++){
      float4 fv = stg[i];
      float2 ww = w1p[i*32 + lane];
      a00 = __fmaf_rn(fv.x, ww.x, a00); a10 = __fmaf_rn(fv.x, ww.y, a10);
      a01 = __fmaf_rn(fv.y, ww.x, a01); a11 = __fmaf_rn(fv.y, ww.y, a11);
      a02 = __fmaf_rn(fv.z, ww.x, a02); a12 = __fmaf_rn(fv.z, ww.y, a12);
      a03 = __fmaf_rn(fv.w, ww.x, a03); a13 = __fmaf_rn(fv.w, ww.y, a13);
    }
    __syncwarp();
    stg[lane]      = make_float4(fmaxf(a00,0.f), fmaxf(a01,0.f), fmaxf(a02,0.f), fmaxf(a03,0.f));
    stg[32 + lane] = make_float4(fmaxf(a10,0.f), fmaxf(a11,0.f), fmaxf(a12,0.f), fmaxf(a13,0.f));
    __syncwarp();

    float bo0 = s_b2[lane], bo1 = s_b2[lane + 32];
    float o00=bo0, o01=bo0, o02=bo0, o03=bo0;
    float o10=bo1, o11=bo1, o12=bo1, o13=bo1;
#pragma unroll 16
    for (int i = 0; i < 64; i++){
      float4 fv = stg[i];
      float2 ww = w2p[i*32 + lane];
      o00 = __fmaf_rn(fv.x, ww.x, o00); o10 = __fmaf_rn(fv.x, ww.y, o10);
      o01 = __fmaf_rn(fv.y, ww.x, o01); o11 = __fmaf_rn(fv.y, ww.y, o11);
      o02 = __fmaf_rn(fv.z, ww.x, o02); o12 = __fmaf_rn(fv.z, ww.y, o12);
      o03 = __fmaf_rn(fv.w, ww.x, o03); o13 = __fmaf_rn(fv.w, ww.y, o13);
    }

#pragma unroll
    for (int q = 0; q < 4; q++){
      int u = base + q;
      if (u < p.N){
        float v0 = (q==0) ? o00 : (q==1) ? o01 : (q==2) ? o02 : o03;
        float v1 = (q==0) ? o10 : (q==1) ? o11 : (q==2) ? o12 : o13;
        p.out[(size_t)u*64 + lane]      = v0;
        p.out[(size_t)u*64 + 32 + lane] = v1;
      }
    }
  }
}

extern "C" void kernel_launch(void* const* d_in, const int* in_sizes, int n_in,
                              void* d_out, int out_size) {
  long maxsz = 0;
  for (int i = 0; i < n_in; i++) if ((long)in_sizes[i] > maxsz) maxsz = in_sizes[i];
  const int T = (int)(maxsz / 2);

  const float2* loc = 0;
  const float*  ts  = 0;
  const int*    cat = 0;
  const int*    seg = 0;
  const float*  w[20];
  int nw_ = 0, nT = 0;

  for (int i = 0; i < n_in; i++) {
    long sz = in_sizes[i];
    if (sz == 2L * T) {
      loc = (const float2*)d_in[i];
    } else if (sz == (long)T) {
      if      (nT == 0) ts  = (const float*)d_in[i];
      else if (nT == 1) cat = (const int*)d_in[i];
      else              seg = (const int*)d_in[i];
      nT++;
    } else if (sz == 1) {
      // num_users scalar — derived from out_size instead
    } else if (nw_ < 20) {
      w[nw_++] = (const float*)d_in[i];
    }
  }

  int N = out_size / 64;
  if (N > MAXN) N = MAXN;

  int ngrp = (T + 3) / 4;
  starts_kernel<<<(ngrp + 255) / 256, 256>>>((const int4*)seg, seg, T, N);

  KParams p;
  p.loc = loc; p.ts = ts; p.cat = cat;
  for (int k = 0; k < 16; k++) p.sw[k] = w[k];
  p.wc1 = w[16];
  p.bc1 = w[17];
  p.wc2 = w[18];
  p.bc2 = w[19];
  p.out = (float*)d_out;
  p.N = N;

  mobility_kernel<<<1184, 256>>>(p);
}

// round 17
// speedup vs baseline: 1.1953x; 1.1953x over previous
#include <cuda_runtime.h>

#define FULLM 0xffffffffu
#define MAXN 200000
#define KSLOT 4

__device__ int g_starts[MAXN + 1];

struct KParams {
  const float2* loc;
  const float*  ts;
  const int*    cat;
  const float*  sw[16];
  const float*  wc1; const float* bc1;
  const float*  wc2; const float* bc2;
  float* out;
  int N;
};

__device__ __forceinline__ float wsum(float v){
#pragma unroll
  for (int o=16;o;o>>=1) v += __shfl_xor_sync(FULLM, v, o);
  return v;
}

// fast positive fmod: trunc-quotient + exact fma + range fixup.
__device__ __forceinline__ float fast_mod(float x, float y, float inv){
  float q = truncf(x * inv);
  float r = __fmaf_rn(-q, y, x);
  r = (r < 0.f)  ? (r + y) : r;
  r = (r >= y)   ? (r - y) : r;
  return r;
}

__global__ void starts_kernel(const int4* __restrict__ seg4,
                              const int*  __restrict__ seg, int T, int N){
  int g = blockIdx.x*blockDim.x + threadIdx.x;
  int base = g * 4;
  if (base >= T) return;
  int4 v = seg4[g];
  if (base == 0){
    g_starts[v.x] = 0;
    g_starts[N] = T;
  } else {
    int prev = seg[base-1];
    if (v.x != prev) g_starts[v.x] = base;
  }
  if (base+1 < T && v.y != v.x) g_starts[v.y] = base+1;
  if (base+2 < T && v.z != v.y) g_starts[v.z] = base+2;
  if (base+3 < T && v.w != v.z) g_starts[v.w] = base+3;
}

__global__ void __launch_bounds__(256) mobility_kernel(KParams p){
  __shared__ float s_w1[4096];   // interleaved: [i*64+m*2+{0,1}] = wc1[i*64+m], wc1[i*64+m+32]
  __shared__ float s_w2[4096];
  __shared__ float s_b1[64];
  __shared__ float s_b2[64];
  __shared__ float s_small[1456];
  __shared__ float4 s_stage[8*64];   // per-warp 64-row feat/hidden staging

  for (int t = threadIdx.x; t < 2048; t += blockDim.x){
    int i = t >> 5, m = t & 31;
    s_w1[2*t]   = p.wc1[i*64 + m];
    s_w1[2*t+1] = p.wc1[i*64 + m + 32];
    s_w2[2*t]   = p.wc2[i*64 + m];
    s_w2[2*t+1] = p.wc2[i*64 + m + 32];
  }
  if (threadIdx.x < 64){
    s_b1[threadIdx.x] = p.bc1[threadIdx.x];
    s_b2[threadIdx.x] = p.bc2[threadIdx.x];
  }
  {
    const int SOFF[17] = {0,32,48,304,320,368,384,640,656,816,832,1088,1104,1168,1184,1440,1456};
#pragma unroll
    for (int sg = 0; sg < 16; sg++){
      int o = SOFF[sg], n = SOFF[sg+1]-o;
      for (int t = threadIdx.x; t < n; t += blockDim.x) s_small[o+t] = p.sw[sg][t];
    }
  }
  __syncthreads();

  const int lane = threadIdx.x & 31;
  const int wid  = threadIdx.x >> 5;
  float4* stg  = &s_stage[wid * 64];
  float*  stgF = (float*)stg;
  const int gw  = (blockIdx.x*blockDim.x + threadIdx.x) >> 5;
  const int nwp = (gridDim.x*blockDim.x) >> 5;
  const float2* w1p = (const float2*)s_w1;
  const float2* w2p = (const float2*)s_w2;

  const int j    = lane & 15;
  const int half = lane >> 4;
  const int sb   = half << 4;

  for (int base = gw*4; base < p.N; base += nwp*4){

    // =================== feature + small-MLP phase (per user) ===================
    for (int q = 0; q < 4; q++){
      int u = base + q;
      if (u >= p.N) break;                       // warp-uniform

      const int s = g_starts[u], e = g_starts[u+1];
      const int L = e - s;
      const float fL = (float)L;

      float hx, hy, t0, t1, t2, radius, diversity, freq, regl;
      unsigned hw0 = 0u, hw1 = 0u, hw2 = 0u;

      if (L <= 32*KSLOT) {
        // ---------- fast path: segment cached in registers ----------
        const int K = (L + 31) >> 5;
        float lx[KSLOT], ly[KSLOT], lt[KSLOT];
        int   lk[KSLOT];

        float sx=0.f, sy=0.f, sh=0.f, sdy=0.f, smo=0.f;
        float tmn = 3.0e38f, tmx = 0.0f;         // ts >= 0; max init 0 is safe

#pragma unroll
        for (int a = 0; a < KSLOT; a++){
          int i = s + a*32 + lane;
          bool v = (a < K) && (i < e);
          float2 pt = make_float2(0.f, 0.f);
          float t = 0.f; int c = 12;
          if (v){ pt = p.loc[i]; t = p.ts[i]; c = p.cat[i]; }
          lx[a] = pt.x; ly[a] = pt.y; lt[a] = t;
          int kx = __float2int_rn(pt.x * 50.0f);
          int ky = __float2int_rn(pt.y * 50.0f);
          lk[a] = v ? (int)(((unsigned)(kx & 0xffff) << 16) | (unsigned)(ky & 0xffff))
                    : 0x7f000000;
          if (v){
            sx += pt.x; sy += pt.y;
            sh  += fast_mod(t, 86400.0f, 1.0f/86400.0f) * (1.0f/3600.0f);
            sdy += fast_mod(t * (1.0f/86400.0f),   7.0f, 1.0f/7.0f);
            smo += fast_mod(t * (1.0f/2592000.0f), 12.0f, 1.0f/12.0f);
            unsigned inc = 1u << ((c & 3) * 8);
            int wq = c >> 2;
            hw0 += (wq==0) ? inc : 0u;
            hw1 += (wq==1) ? inc : 0u;
            hw2 += (wq==2) ? inc : 0u;
            tmn = fminf(tmn, t); tmx = fmaxf(tmx, t);
          }
        }

        // diffs via shfl of cached timestamps; accumulate sum and sum-of-squares
        float sdiff = 0.f, sdiff2 = 0.f;
#pragma unroll
        for (int a = 0; a < KSLOT; a++){
          float up = (a+1 < KSLOT) ? __shfl_sync(FULLM, lt[a+1], 0) : 0.f;
          float nt = __shfl_down_sync(FULLM, lt[a], 1);
          if (lane == 31) nt = up;
          int i = s + a*32 + lane;
          bool hd = (a < K) && (i < e - 1);
          float d = nt - lt[a];
          sdiff  += hd ? d : 0.f;
          sdiff2 += hd ? d*d : 0.f;
        }

        // distances: sum and sum-of-squares (variance via identity)
        float sdl = 0.f, sdd = 0.f;
        {
          // need home first -> reduce position sums early
          sx = wsum(sx); sy = wsum(sy);
          hx = sx / fL; hy = sy / fL;
        }
#pragma unroll
        for (int a = 0; a < KSLOT; a++){
          int i = s + a*32 + lane;
          bool v = (a < K) && (i < e);
          float dx = lx[a] - hx, dy = ly[a] - hy;
          float dd = sqrtf(dx*dx + dy*dy);
          sdl += v ? dd : 0.f;
          sdd += v ? dd*dd : 0.f;
        }

        sh = wsum(sh); sdy = wsum(sdy); smo = wsum(smo);
        sdiff = wsum(sdiff); sdiff2 = wsum(sdiff2);
        sdl = wsum(sdl); sdd = wsum(sdd);
        hw0 = __reduce_add_sync(FULLM, hw0);
        hw1 = __reduce_add_sync(FULLM, hw1);
        hw2 = __reduce_add_sync(FULLM, hw2);
        tmn = __uint_as_float(__reduce_min_sync(FULLM, __float_as_uint(tmn)));
        tmx = __uint_as_float(__reduce_max_sync(FULLM, __float_as_uint(tmx)));

        t0 = sh / fL; t1 = sdy / fL; t2 = smo / fL;
        const float span = (tmx - tmn) / 86400.0f;
        freq = fL / fmaxf(span, 1.0f);

        const float dmu  = sdiff / (fL - 1.0f);
        const float sdvv = fmaxf(sdiff2 - (fL - 1.0f) * dmu * dmu, 0.f);
        const float dvar = sdvv / (fL - 2.0f);
        regl = 1.0f / (sqrtf(dvar) + 1e-6f);

        const float dmean = sdl / fL;
        const float srr   = fmaxf(sdd - fL * dmean * dmean, 0.f);
        radius = sqrtf(srr / (fL - 1.0f));

        // diversity: MATCH.ANY within slot + broadcast compare across slots
        unsigned uniqcnt = 0u;
        const unsigned ltmask = (1u << lane) - 1u;
#pragma unroll
        for (int a = 0; a < KSLOT; a++){
          if (a >= K) break;
          int i = s + a*32 + lane;
          bool valid = (i < e);
          int ka = lk[a];
          unsigned m = __match_any_sync(FULLM, ka);
          bool dup = (m & ltmask) != 0u;
#pragma unroll
          for (int b = 0; b < KSLOT-1; b++){
            if (b >= a) break;
            int kb = lk[b];
#pragma unroll
            for (int r = 0; r < 32; r++){
              int kj = __shfl_sync(FULLM, kb, r);
              dup |= (kj == ka);
            }
          }
          uniqcnt += (valid && !dup) ? 1u : 0u;
        }
        float uniq = (float)__reduce_add_sync(FULLM, uniqcnt);
        diversity = uniq / fL;

      } else {
        // ---------- fallback path (L > 128): global-load version ----------
        float sx=0.f, sy=0.f, sh=0.f, sdy=0.f, smo=0.f, sdiff=0.f;
        float tmn = 3.0e38f, tmx = 0.0f;
        for (int i = s + lane; i < e; i += 32){
          float2 pt = p.loc[i];
          float t  = p.ts[i];
          int   c  = p.cat[i];
          sx += pt.x; sy += pt.y;
          sh  += __fdiv_rn(fmodf(t, 86400.0f), 3600.0f);
          sdy += fmodf(__fdiv_rn(t, 86400.0f), 7.0f);
          smo += fmodf(__fdiv_rn(t, 2592000.0f), 12.0f);
          unsigned inc = 1u << ((c & 3) * 8);
          int wq = c >> 2;
          hw0 += (wq==0) ? inc : 0u;
          hw1 += (wq==1) ? inc : 0u;
          hw2 += (wq==2) ? inc : 0u;
          tmn = fminf(tmn, t); tmx = fmaxf(tmx, t);
          if (i + 1 < e) sdiff += p.ts[i+1] - t;
        }
        sx = wsum(sx); sy = wsum(sy);
        sh = wsum(sh); sdy = wsum(sdy); smo = wsum(smo);
        sdiff = wsum(sdiff);
        hw0 = __reduce_add_sync(FULLM, hw0);
        hw1 = __reduce_add_sync(FULLM, hw1);
        hw2 = __reduce_add_sync(FULLM, hw2);
        tmn = __uint_as_float(__reduce_min_sync(FULLM, __float_as_uint(tmn)));
        tmx = __uint_as_float(__reduce_max_sync(FULLM, __float_as_uint(tmx)));

        hx = sx / fL; hy = sy / fL;
        t0 = sh / fL; t1 = sdy / fL; t2 = smo / fL;
        const float dmu  = sdiff / (fL - 1.0f);
        const float span = (tmx - tmn) / 86400.0f;
        freq = fL / fmaxf(span, 1.0f);

        float sdl = 0.f, sdv = 0.f;
        for (int i = s + lane; i < e; i += 32){
          float2 pt = p.loc[i];
          float dx = pt.x - hx, dy = pt.y - hy;
          sdl += sqrtf(dx*dx + dy*dy);
          if (i + 1 < e){
            float dd = p.ts[i+1] - p.ts[i] - dmu;
            sdv += dd * dd;
          }
        }
        sdl = wsum(sdl); sdv = wsum(sdv);
        const float dmean = sdl / fL;
        const float dvar  = sdv / (fL - 2.0f);
        regl = 1.0f / (sqrtf(dvar) + 1e-6f);

        float srr = 0.f;
        for (int i = s + lane; i < e; i += 32){
          float2 pt = p.loc[i];
          float dx = pt.x - hx, dy = pt.y - hy;
          float r = sqrtf(dx*dx + dy*dy) - dmean;
          srr += r * r;
        }
        srr = wsum(srr);
        radius = sqrtf(srr / (fL - 1.0f));

        float uniqp = 0.f;
        for (int bb = s; bb < e; bb += 32){
          int i = bb + lane;
          bool valid = (i < e);
          float px = 0.f, py = 0.f;
          if (valid){ float2 pt = p.loc[i]; px = pt.x; py = pt.y; }
          bool dup = false;
          int jmax = min(bb + 31, e - 1);
          for (int jg = s; jg < jmax; ++jg){
            float2 qq = p.loc[jg];
            dup |= (jg < i) & (qq.x == px) & (qq.y == py);
          }
          uniqp += (valid && !dup) ? 1.f : 0.f;
        }
        float uniq = wsum(uniqp);
        diversity = uniq / fL;
      }

      // category distribution
      float actv[10];
#pragma unroll
      for (int c = 0; c < 10; c++){
        unsigned w = (c < 4) ? hw0 : ((c < 8) ? hw1 : hw2);
        unsigned cnt = (w >> ((c & 3) * 8)) & 0xffu;
        actv[c] = (float)cnt / fL;
      }

      // ---------------- small MLPs (smem weights, cooperative) ----------------
      float hv0;
      {
        int w1o = half ? 320 : 0;
        int b1o = half ? 368 : 32;
        float x0 = half ? t0 : hx;
        float x1 = half ? t1 : hy;
        float x2 = half ? t2 : 0.f;
        float a = s_small[b1o + j];
        a += x0 * s_small[w1o +  0 + j];
        a += x1 * s_small[w1o + 16 + j];
        a += x2 * s_small[w1o + 32 + j];
        hv0 = fmaxf(a, 0.f);
      }
      float hv1;
      {
        int w1o = half ? 1104 : 656;
        int b1o = half ? 1168 : 816;
        float xv[10];
        xv[0] = half ? radius    : actv[0];
        xv[1] = half ? diversity : actv[1];
        xv[2] = half ? freq      : actv[2];
        xv[3] = half ? regl      : actv[3];
#pragma unroll
        for (int i = 4; i < 10; i++) xv[i] = half ? 0.f : actv[i];
        float a = s_small[b1o + j];
#pragma unroll
        for (int i = 0; i < 10; i++) a += xv[i] * s_small[w1o + i*16 + j];
        hv1 = fmaxf(a, 0.f);
      }

      float f0, f1;
      {
        int w2o = half ? 384 : 48;
        int b2o = half ? 640 : 304;
        float a = s_small[b2o + j];
#pragma unroll
        for (int i = 0; i < 16; i++)
          a += __shfl_sync(FULLM, hv0, sb + i) * s_small[w2o + i*16 + j];
        f0 = a;
      }
      {
        int w2o = half ? 1184 : 832;
        int b2o = half ? 1440 : 1088;
        float a = s_small[b2o + j];
#pragma unroll
        for (int i = 0; i < 16; i++)
          a += __shfl_sync(FULLM, hv1, sb + i) * s_small[w2o + i*16 + j];
        f1 = a;
      }

      // stage this user's feats (component q of the float4 rows)
      stgF[lane*4 + q]      = f0;
      stgF[(32+lane)*4 + q] = f1;
    }
    __syncwarp();

    // =================== batched cmb MLP: 4 users per pass ===================
    float bi0 = s_b1[lane], bi1 = s_b1[lane + 32];
    float a00=bi0, a01=bi0, a02=bi0, a03=bi0;
    float a10=bi1, a11=bi1, a12=bi1, a13=bi1;
#pragma unroll 16
    for (int i = 0; i < 64; i++){
      float4 fv = stg[i];
      float2 ww = w1p[i*32 + lane];
      a00 = __fmaf_rn(fv.x, ww.x, a00); a10 = __fmaf_rn(fv.x, ww.y, a10);
      a01 = __fmaf_rn(fv.y, ww.x, a01); a11 = __fmaf_rn(fv.y, ww.y, a11);
      a02 = __fmaf_rn(fv.z, ww.x, a02); a12 = __fmaf_rn(fv.z, ww.y, a12);
      a03 = __fmaf_rn(fv.w, ww.x, a03); a13 = __fmaf_rn(fv.w, ww.y, a13);
    }
    __syncwarp();
    stg[lane]      = make_float4(fmaxf(a00,0.f), fmaxf(a01,0.f), fmaxf(a02,0.f), fmaxf(a03,0.f));
    stg[32 + lane] = make_float4(fmaxf(a10,0.f), fmaxf(a11,0.f), fmaxf(a12,0.f), fmaxf(a13,0.f));
    __syncwarp();

    float bo0 = s_b2[lane], bo1 = s_b2[lane + 32];
    float o00=bo0, o01=bo0, o02=bo0, o03=bo0;
    float o10=bo1, o11=bo1, o12=bo1, o13=bo1;
#pragma unroll 16
    for (int i = 0; i < 64; i++){
      float4 fv = stg[i];
      float2 ww = w2p[i*32 + lane];
      o00 = __fmaf_rn(fv.x, ww.x, o00); o10 = __fmaf_rn(fv.x, ww.y, o10);
      o01 = __fmaf_rn(fv.y, ww.x, o01); o11 = __fmaf_rn(fv.y, ww.y, o11);
      o02 = __fmaf_rn(fv.z, ww.x, o02); o12 = __fmaf_rn(fv.z, ww.y, o12);
      o03 = __fmaf_rn(fv.w, ww.x, o03); o13 = __fmaf_rn(fv.w, ww.y, o13);
    }

#pragma unroll
    for (int q = 0; q < 4; q++){
      int u = base + q;
      if (u < p.N){
        float v0 = (q==0) ? o00 : (q==1) ? o01 : (q==2) ? o02 : o03;
        float v1 = (q==0) ? o10 : (q==1) ? o11 : (q==2) ? o12 : o13;
        p.out[(size_t)u*64 + lane]      = v0;
        p.out[(size_t)u*64 + 32 + lane] = v1;
      }
    }
  }
}

extern "C" void kernel_launch(void* const* d_in, const int* in_sizes, int n_in,
                              void* d_out, int out_size) {
  long maxsz = 0;
  for (int i = 0; i < n_in; i++) if ((long)in_sizes[i] > maxsz) maxsz = in_sizes[i];
  const int T = (int)(maxsz / 2);

  const float2* loc = 0;
  const float*  ts  = 0;
  const int*    cat = 0;
  const int*    seg = 0;
  const float*  w[20];
  int nw_ = 0, nT = 0;

  for (int i = 0; i < n_in; i++) {
    long sz = in_sizes[i];
    if (sz == 2L * T) {
      loc = (const float2*)d_in[i];
    } else if (sz == (long)T) {
      if      (nT == 0) ts  = (const float*)d_in[i];
      else if (nT == 1) cat = (const int*)d_in[i];
      else              seg = (const int*)d_in[i];
      nT++;
    } else if (sz == 1) {
      // num_users scalar — derived from out_size instead
    } else if (nw_ < 20) {
      w[nw_++] = (const float*)d_in[i];
    }
  }

  int N = out_size / 64;
  if (N > MAXN) N = MAXN;

  int ngrp = (T + 3) / 4;
  starts_kernel<<<(ngrp + 255) / 256, 256>>>((const int4*)seg, seg, T, N);

  KParams p;
  p.loc = loc; p.ts = ts; p.cat = cat;
  for (int k = 0; k < 16; k++) p.sw[k] = w[k];
  p.wc1 = w[16];
  p.bc1 = w[17];
  p.wc2 = w[18];
  p.bc2 = w[19];
  p.out = (float*)d_out;
  p.N = N;

  mobility_kernel<<<1184, 256>>>(p);
}